// round 12
// baseline (speedup 1.0000x reference)
#include <cuda_runtime.h>

#define B_DIM 8
#define CIN 512
#define COUT 3
#define WDIM 512
#define HW 65536           // 256*256
#define CONV_CLAMP 256.0f

#define N_PROD 16          // producer CTAs per batch (each covers 32 channels)
#define N_CONS 64          // consumer (streaming) CTAs per batch

// Staging for per-(batch, channel) coefficient triples:
//   g_m4[b*CIN+c] = (weight[0][c], weight[1][c], weight[2][c], 0) * styles[b][c]
__device__ float4 g_m4[B_DIM * CIN];

// Monotonic counters (never reset; epoch-derived targets make graph replays
// deterministic): producers bump done[b]; consumers bump cons[b] to learn
// their replay epoch E and wait for done[b] >= N_PROD * E.
__device__ unsigned int g_done[B_DIM];
__device__ unsigned int g_cons[B_DIM];

// ---------------------------------------------------------------------------
// Single kernel, two roles by blockIdx.x. grid = (80, 8), block = 256.
// All 640 CTAs fit in one wave: __launch_bounds__(256, 5) caps regs at 51
// -> 5 CTAs/SM x 148 SMs = 740 slots >= 640, so the spin cannot deadlock.
//
// bx < 16  (producers, lowest bids -> dispatched first):
//   warp w computes 4 channel dots (c = bx*32 + w*4 + i) with ILP across
//   the 4 rows, writes g_m4, __threadfence, one atomicAdd on g_done[b], exit.
// bx >= 16 (consumers, stripe sx = bx-16):
//   tid0 derives epoch E from g_cons[b]; all threads preload x rows 0..3
//   (__ldcs, real stream work) while producers finish; tid0 spins on
//   g_done[b] >= 16E; coeff fill; peeled c=0..3; frozen loop c=4..512.
// ---------------------------------------------------------------------------
__global__ void __launch_bounds__(256, 5)
torgb_pc_kernel(const float* __restrict__ x,
                const float* __restrict__ w,
                const float* __restrict__ weight,
                const float* __restrict__ bias,
                const float* __restrict__ affine_w,
                const float* __restrict__ affine_b,
                float* __restrict__ out)
{
    const int b    = blockIdx.y;
    const int bx   = blockIdx.x;
    const int tid  = threadIdx.x;
    const int warp = tid >> 5;
    const int lane = tid & 31;

    if (bx < N_PROD) {
        // ================= PRODUCER =================
        const int cBase = bx * 32 + warp * 4;        // 4 channels per warp
        const float* __restrict__ wrow = w + (size_t)b * WDIM;
        const float* __restrict__ a0p = affine_w + (size_t)(cBase + 0) * WDIM;
        const float* __restrict__ a1p = affine_w + (size_t)(cBase + 1) * WDIM;
        const float* __restrict__ a2p = affine_w + (size_t)(cBase + 2) * WDIM;
        const float* __restrict__ a3p = affine_w + (size_t)(cBase + 3) * WDIM;

        float s0 = 0.f, s1 = 0.f, s2 = 0.f, s3 = 0.f;
#pragma unroll
        for (int j = 0; j < WDIM / 32; ++j) {
            const int k = lane + 32 * j;
            const float wv = __ldg(&wrow[k]);
            s0 = fmaf(__ldg(&a0p[k]), wv, s0);
            s1 = fmaf(__ldg(&a1p[k]), wv, s1);
            s2 = fmaf(__ldg(&a2p[k]), wv, s2);
            s3 = fmaf(__ldg(&a3p[k]), wv, s3);
        }
#pragma unroll
        for (int off = 16; off > 0; off >>= 1) {
            s0 += __shfl_xor_sync(0xffffffffu, s0, off);
            s1 += __shfl_xor_sync(0xffffffffu, s1, off);
            s2 += __shfl_xor_sync(0xffffffffu, s2, off);
            s3 += __shfl_xor_sync(0xffffffffu, s3, off);
        }

        if (lane == 0) {
            const float affine_gain = 1.0f / sqrtf((float)WDIM);
            const float cin_gain    = 1.0f / sqrtf((float)CIN);
            float sums[4] = {s0, s1, s2, s3};
#pragma unroll
            for (int i = 0; i < 4; ++i) {
                const int c = cBase + i;
                const float style =
                    (sums[i] * affine_gain + affine_b[c]) * cin_gain;
                float4 m;
                m.x = weight[0 * CIN + c] * style;
                m.y = weight[1 * CIN + c] * style;
                m.z = weight[2 * CIN + c] * style;
                m.w = 0.0f;
                g_m4[b * CIN + c] = m;
            }
        }
        __syncthreads();                  // all 8 warps' writes issued
        if (tid == 0) {
            __threadfence();              // publish (release)
            atomicAdd(&g_done[b], 1u);
        }
        return;                           // free the slot
    }

    // ================= CONSUMER =================
    __shared__ float m0[CIN];
    __shared__ float m1[CIN];
    __shared__ float m2[CIN];
    __shared__ unsigned int s_target;

    const int sx  = bx - N_PROD;          // streaming stripe 0..63
    const int hw4 = sx * blockDim.x + tid;
    const float4* __restrict__ x4 =
        (const float4*)(x + (size_t)b * CIN * HW);

    // Derive replay epoch (monotonic counters, no reset needed).
    if (tid == 0) {
        const unsigned int start = atomicAdd(&g_cons[b], 1u);
        const unsigned int E = start / (unsigned)N_CONS + 1u;
        s_target = E * (unsigned)N_PROD;
    }

    // Preload first 4 stream rows while producers run (real DRAM work).
    const float4 p0 = __ldcs(&x4[(size_t)0 * (HW / 4) + hw4]);
    const float4 p1 = __ldcs(&x4[(size_t)1 * (HW / 4) + hw4]);
    const float4 p2 = __ldcs(&x4[(size_t)2 * (HW / 4) + hw4]);
    const float4 p3 = __ldcs(&x4[(size_t)3 * (HW / 4) + hw4]);

    // Wait for this batch's 16 producers.
    __syncthreads();                      // s_target visible
    if (tid == 0) {
        const unsigned int target = s_target;
        volatile unsigned int* ctr = &g_done[b];
        while (*ctr < target)
            __nanosleep(32);
        __threadfence();                  // acquire
    }
    __syncthreads();

    // Coefficient fill for batch b (L2 via __ldcg).
    for (int c = tid; c < CIN; c += blockDim.x) {
        const float4 m = __ldcg(&g_m4[b * CIN + c]);
        m0[c] = m.x;
        m1[c] = m.y;
        m2[c] = m.z;
    }
    __syncthreads();

    float4 a0 = make_float4(0.f, 0.f, 0.f, 0.f);
    float4 a1 = make_float4(0.f, 0.f, 0.f, 0.f);
    float4 a2 = make_float4(0.f, 0.f, 0.f, 0.f);

#define FMA3(xv, c)                                                       \
    {                                                                     \
        const float c0 = m0[(c)];                                         \
        const float c1 = m1[(c)];                                         \
        const float c2 = m2[(c)];                                         \
        a0.x = fmaf((xv).x, c0, a0.x); a0.y = fmaf((xv).y, c0, a0.y);     \
        a0.z = fmaf((xv).z, c0, a0.z); a0.w = fmaf((xv).w, c0, a0.w);     \
        a1.x = fmaf((xv).x, c1, a1.x); a1.y = fmaf((xv).y, c1, a1.y);     \
        a1.z = fmaf((xv).z, c1, a1.z); a1.w = fmaf((xv).w, c1, a1.w);     \
        a2.x = fmaf((xv).x, c2, a2.x); a2.y = fmaf((xv).y, c2, a2.y);     \
        a2.z = fmaf((xv).z, c2, a2.z); a2.w = fmaf((xv).w, c2, a2.w);     \
    }
    // Peeled rows consuming the preloads.
    FMA3(p0, 0)
    FMA3(p1, 1)
    FMA3(p2, 2)
    FMA3(p3, 3)

    // Frozen R3 stream body, single fixed-bound loop.
#pragma unroll 4
    for (int c = 4; c < CIN; ++c) {
        const float4 xv = __ldcs(&x4[(size_t)c * (HW / 4) + hw4]);
        FMA3(xv, c)
    }
#undef FMA3

    const float bv0 = bias[0];
    const float bv1 = bias[1];
    const float bv2 = bias[2];

#define CLAMP1(v) fminf(fmaxf((v), -CONV_CLAMP), CONV_CLAMP)
    float4 o0 = make_float4(CLAMP1(a0.x + bv0), CLAMP1(a0.y + bv0),
                            CLAMP1(a0.z + bv0), CLAMP1(a0.w + bv0));
    float4 o1 = make_float4(CLAMP1(a1.x + bv1), CLAMP1(a1.y + bv1),
                            CLAMP1(a1.z + bv1), CLAMP1(a1.w + bv1));
    float4 o2 = make_float4(CLAMP1(a2.x + bv2), CLAMP1(a2.y + bv2),
                            CLAMP1(a2.z + bv2), CLAMP1(a2.w + bv2));
#undef CLAMP1

    float4* __restrict__ out4 = (float4*)out;
    const size_t obase = (size_t)b * COUT * (HW / 4);
    __stcs(&out4[obase + 0 * (HW / 4) + hw4], o0);
    __stcs(&out4[obase + 1 * (HW / 4) + hw4], o1);
    __stcs(&out4[obase + 2 * (HW / 4) + hw4], o2);
}

// ---------------------------------------------------------------------------
// Launch
//   d_in[0] = x        [B, CIN, H, W]  f32
//   d_in[1] = w        [B, WDIM]       f32
//   d_in[2] = weight   [COUT, CIN,1,1] f32
//   d_in[3] = bias     [COUT]          f32
//   d_in[4] = affine_w [CIN, WDIM]     f32
//   d_in[5] = affine_b [CIN]           f32
// ---------------------------------------------------------------------------
extern "C" void kernel_launch(void* const* d_in, const int* in_sizes, int n_in,
                              void* d_out, int out_size)
{
    const float* x        = (const float*)d_in[0];
    const float* w        = (const float*)d_in[1];
    const float* weight   = (const float*)d_in[2];
    const float* bias     = (const float*)d_in[3];
    const float* affine_w = (const float*)d_in[4];
    const float* affine_b = (const float*)d_in[5];
    float* out = (float*)d_out;

    dim3 cgrid(N_PROD + N_CONS, B_DIM);   // (80, 8) = 640 CTAs, single wave
    torgb_pc_kernel<<<cgrid, 256>>>(x, w, weight, bias,
                                    affine_w, affine_b, out);
}

// round 13
// speedup vs baseline: 1.0030x; 1.0030x over previous
#include <cuda_runtime.h>

#define B_DIM 8
#define CIN 512
#define COUT 3
#define WDIM 512
#define HW 65536           // 256*256
#define CONV_CLAMP 256.0f

// Staging for per-(batch, channel) coefficient triples:
//   g_m4[b*CIN+c] = (weight[0][c], weight[1][c], weight[2][c], 0) * styles[b][c]
__device__ float4 g_m4[B_DIM * CIN];

// Per-batch arrival counters (monotonic across graph replays; cohort = 64 CTAs.
// target = (start/64+1)*64, so no reset is needed -> deterministic per run).
__device__ unsigned int g_bar[B_DIM];

// ---------------------------------------------------------------------------
// Fused kernel = EXACT R7 (verified 155.74us kernel) with ONE change:
// phase-1 dot loads are float4 (4 independent LDG.128 per lane instead of a
// 16-deep scalar chain) -> shorter phase-1 critical path -> earlier cohort
// completion -> smaller barrier window. Everything else untouched:
// nanosleep spin, no preload, no prefetch, frozen 0..512 stream loop.
// grid = (64, 8), block = 256; all 512 CTAs co-resident (592 slots).
// ---------------------------------------------------------------------------
__global__ void __launch_bounds__(256)
torgb_fused_kernel(const float* __restrict__ x,
                   const float* __restrict__ w,
                   const float* __restrict__ weight,
                   const float* __restrict__ bias,
                   const float* __restrict__ affine_w,
                   const float* __restrict__ affine_b,
                   float* __restrict__ out)
{
    __shared__ float m0[CIN];
    __shared__ float m1[CIN];
    __shared__ float m2[CIN];

    const int b    = blockIdx.y;
    const int bx   = blockIdx.x;
    const int tid  = threadIdx.x;
    const int warp = tid >> 5;
    const int lane = tid & 31;

    // ---- Phase 1: compute this CTA's 8 coefficients (c = bx*8 + warp) ----
    //      float4 loads: 4 independent LDG.128 per lane (R13's one change).
    {
        const int c = bx * 8 + warp;
        const float4* __restrict__ arow4 =
            (const float4*)(affine_w + (size_t)c * WDIM);
        const float4* __restrict__ wrow4 =
            (const float4*)(w + (size_t)b * WDIM);
        float sum = 0.0f;
#pragma unroll
        for (int j = 0; j < WDIM / 128; ++j) {          // 4 iterations
            const int k = lane + 32 * j;
            const float4 av = __ldg(&arow4[k]);
            const float4 wv = __ldg(&wrow4[k]);
            sum = fmaf(av.x, wv.x, sum);
            sum = fmaf(av.y, wv.y, sum);
            sum = fmaf(av.z, wv.z, sum);
            sum = fmaf(av.w, wv.w, sum);
        }
#pragma unroll
        for (int off = 16; off > 0; off >>= 1)
            sum += __shfl_xor_sync(0xffffffffu, sum, off);

        if (lane == 0) {
            const float affine_gain = 1.0f / sqrtf((float)WDIM);
            const float cin_gain    = 1.0f / sqrtf((float)CIN);
            const float style = (sum * affine_gain + affine_b[c]) * cin_gain;
            float4 m;
            m.x = weight[0 * CIN + c] * style;
            m.y = weight[1 * CIN + c] * style;
            m.z = weight[2 * CIN + c] * style;
            m.w = 0.0f;
            g_m4[b * CIN + c] = m;
        }
    }
    __syncthreads();                 // all warps done writing g_m4

    // ---- Per-batch barrier over the 64 CTAs producing batch b (R7 exact) ----
    if (tid == 0) {
        __threadfence();             // publish our g_m4 writes (release)
        const unsigned int start  = atomicAdd(&g_bar[b], 1u);
        const unsigned int target = (start / 64u + 1u) * 64u;
        volatile unsigned int* ctr = &g_bar[b];
        while (*ctr < target)
            __nanosleep(32);
        __threadfence();             // acquire
    }
    __syncthreads();

    // ---- Coefficient fill for batch b (L2 via __ldcg) ----
    for (int c = tid; c < CIN; c += blockDim.x) {
        const float4 m = __ldcg(&g_m4[b * CIN + c]);
        m0[c] = m.x;
        m1[c] = m.y;
        m2[c] = m.z;
    }
    __syncthreads();

    // ---- Phase 2: the frozen streaming loop (single fixed 0..512) ----
    const int hw4 = bx * blockDim.x + tid;    // index in float4 units
    const float4* __restrict__ x4 =
        (const float4*)(x + (size_t)b * CIN * HW);

    float4 a0 = make_float4(0.f, 0.f, 0.f, 0.f);
    float4 a1 = make_float4(0.f, 0.f, 0.f, 0.f);
    float4 a2 = make_float4(0.f, 0.f, 0.f, 0.f);

#pragma unroll 4
    for (int c = 0; c < CIN; ++c) {
        const float4 xv = __ldcs(&x4[(size_t)c * (HW / 4) + hw4]);
        const float c0 = m0[c];
        const float c1 = m1[c];
        const float c2 = m2[c];
        a0.x = fmaf(xv.x, c0, a0.x); a0.y = fmaf(xv.y, c0, a0.y);
        a0.z = fmaf(xv.z, c0, a0.z); a0.w = fmaf(xv.w, c0, a0.w);
        a1.x = fmaf(xv.x, c1, a1.x); a1.y = fmaf(xv.y, c1, a1.y);
        a1.z = fmaf(xv.z, c1, a1.z); a1.w = fmaf(xv.w, c1, a1.w);
        a2.x = fmaf(xv.x, c2, a2.x); a2.y = fmaf(xv.y, c2, a2.y);
        a2.z = fmaf(xv.z, c2, a2.z); a2.w = fmaf(xv.w, c2, a2.w);
    }

    const float bv0 = bias[0];
    const float bv1 = bias[1];
    const float bv2 = bias[2];

#define CLAMP1(v) fminf(fmaxf((v), -CONV_CLAMP), CONV_CLAMP)
    float4 o0 = make_float4(CLAMP1(a0.x + bv0), CLAMP1(a0.y + bv0),
                            CLAMP1(a0.z + bv0), CLAMP1(a0.w + bv0));
    float4 o1 = make_float4(CLAMP1(a1.x + bv1), CLAMP1(a1.y + bv1),
                            CLAMP1(a1.z + bv1), CLAMP1(a1.w + bv1));
    float4 o2 = make_float4(CLAMP1(a2.x + bv2), CLAMP1(a2.y + bv2),
                            CLAMP1(a2.z + bv2), CLAMP1(a2.w + bv2));
#undef CLAMP1

    float4* __restrict__ out4 = (float4*)out;
    const size_t obase = (size_t)b * COUT * (HW / 4);
    __stcs(&out4[obase + 0 * (HW / 4) + hw4], o0);
    __stcs(&out4[obase + 1 * (HW / 4) + hw4], o1);
    __stcs(&out4[obase + 2 * (HW / 4) + hw4], o2);
}

// ---------------------------------------------------------------------------
// Launch
//   d_in[0] = x        [B, CIN, H, W]  f32
//   d_in[1] = w        [B, WDIM]       f32
//   d_in[2] = weight   [COUT, CIN,1,1] f32
//   d_in[3] = bias     [COUT]          f32
//   d_in[4] = affine_w [CIN, WDIM]     f32
//   d_in[5] = affine_b [CIN]           f32
// ---------------------------------------------------------------------------
extern "C" void kernel_launch(void* const* d_in, const int* in_sizes, int n_in,
                              void* d_out, int out_size)
{
    const float* x        = (const float*)d_in[0];
    const float* w        = (const float*)d_in[1];
    const float* weight   = (const float*)d_in[2];
    const float* bias     = (const float*)d_in[3];
    const float* affine_w = (const float*)d_in[4];
    const float* affine_b = (const float*)d_in[5];
    float* out = (float*)d_out;

    dim3 cgrid(HW / 4 / 256, B_DIM);
    torgb_fused_kernel<<<cgrid, 256>>>(x, w, weight, bias,
                                       affine_w, affine_b, out);
}

// round 14
// speedup vs baseline: 1.0177x; 1.0146x over previous
#include <cuda_runtime.h>

#define B_DIM 8
#define CIN 512
#define COUT 3
#define WDIM 512
#define HW 65536           // 256*256
#define CONV_CLAMP 256.0f

// Staging for per-(batch, channel) coefficient triples:
//   g_m4[b*CIN+c] = (weight[0][c], weight[1][c], weight[2][c], 0) * styles[b][c]
__device__ float4 g_m4[B_DIM * CIN];

// Per-batch arrival counters (monotonic across graph replays; cohort = 64 CTAs.
// target = (start/64+1)*64, so no reset is needed -> deterministic per run).
__device__ unsigned int g_bar[B_DIM];

// Release-increment: orders all prior global writes before the counter bump.
__device__ __forceinline__ unsigned int atom_add_release(unsigned int* p,
                                                         unsigned int v)
{
    unsigned int old;
    asm volatile("atom.add.release.gpu.global.u32 %0, [%1], %2;"
                 : "=r"(old) : "l"(p), "r"(v) : "memory");
    return old;
}

// Acquire-load: orders the counter read before all subsequent global reads.
__device__ __forceinline__ unsigned int ld_acquire(const unsigned int* p)
{
    unsigned int v;
    asm volatile("ld.acquire.gpu.global.u32 %0, [%1];"
                 : "=r"(v) : "l"(p) : "memory");
    return v;
}

// ---------------------------------------------------------------------------
// Fused kernel = EXACT R7 (best measured: 155.74us) with ONE change:
// the barrier's two full __threadfence() (MEMBAR.GPU) are replaced by
// scoped release/acquire atomics on g_bar[b] — identical ordering semantics
// (g_m4 stores released by the arrive, acquired by the spin read), two
// fewer MEMBARs on the critical path. Phase-1 scalar loads, nanosleep spin,
// coeff fill, and the frozen 0..512 stream loop are untouched.
// grid = (64, 8), block = 256; all 512 CTAs co-resident (4/SM x 148 = 592).
// ---------------------------------------------------------------------------
__global__ void __launch_bounds__(256)
torgb_fused_kernel(const float* __restrict__ x,
                   const float* __restrict__ w,
                   const float* __restrict__ weight,
                   const float* __restrict__ bias,
                   const float* __restrict__ affine_w,
                   const float* __restrict__ affine_b,
                   float* __restrict__ out)
{
    __shared__ float m0[CIN];
    __shared__ float m1[CIN];
    __shared__ float m2[CIN];

    const int b    = blockIdx.y;
    const int bx   = blockIdx.x;
    const int tid  = threadIdx.x;
    const int warp = tid >> 5;
    const int lane = tid & 31;

    // ---- Phase 1: compute this CTA's 8 coefficients (c = bx*8 + warp) ----
    //      Scalar loads (R7 exact — float4 here measurably hurts, R13).
    {
        const int c = bx * 8 + warp;
        const float* __restrict__ arow = affine_w + (size_t)c * WDIM;
        const float* __restrict__ wrow = w + (size_t)b * WDIM;
        float sum = 0.0f;
#pragma unroll
        for (int j = 0; j < WDIM / 32; ++j) {
            const int k = lane + 32 * j;
            sum = fmaf(__ldg(&arow[k]), __ldg(&wrow[k]), sum);
        }
#pragma unroll
        for (int off = 16; off > 0; off >>= 1)
            sum += __shfl_xor_sync(0xffffffffu, sum, off);

        if (lane == 0) {
            const float affine_gain = 1.0f / sqrtf((float)WDIM);
            const float cin_gain    = 1.0f / sqrtf((float)CIN);
            const float style = (sum * affine_gain + affine_b[c]) * cin_gain;
            float4 m;
            m.x = weight[0 * CIN + c] * style;
            m.y = weight[1 * CIN + c] * style;
            m.z = weight[2 * CIN + c] * style;
            m.w = 0.0f;
            g_m4[b * CIN + c] = m;
        }
    }
    __syncthreads();                 // all warps done writing g_m4

    // ---- Per-batch barrier (release/acquire atomics, no MEMBAR.GPU) ----
    if (tid == 0) {
        const unsigned int start  = atom_add_release(&g_bar[b], 1u);
        const unsigned int target = (start / 64u + 1u) * 64u;
        while (ld_acquire(&g_bar[b]) < target)
            __nanosleep(32);
    }
    __syncthreads();

    // ---- Coefficient fill for batch b (L2 via __ldcg) ----
    for (int c = tid; c < CIN; c += blockDim.x) {
        const float4 m = __ldcg(&g_m4[b * CIN + c]);
        m0[c] = m.x;
        m1[c] = m.y;
        m2[c] = m.z;
    }
    __syncthreads();

    // ---- Phase 2: the frozen streaming loop (single fixed 0..512) ----
    const int hw4 = bx * blockDim.x + tid;    // index in float4 units
    const float4* __restrict__ x4 =
        (const float4*)(x + (size_t)b * CIN * HW);

    float4 a0 = make_float4(0.f, 0.f, 0.f, 0.f);
    float4 a1 = make_float4(0.f, 0.f, 0.f, 0.f);
    float4 a2 = make_float4(0.f, 0.f, 0.f, 0.f);

#pragma unroll 4
    for (int c = 0; c < CIN; ++c) {
        const float4 xv = __ldcs(&x4[(size_t)c * (HW / 4) + hw4]);
        const float c0 = m0[c];
        const float c1 = m1[c];
        const float c2 = m2[c];
        a0.x = fmaf(xv.x, c0, a0.x); a0.y = fmaf(xv.y, c0, a0.y);
        a0.z = fmaf(xv.z, c0, a0.z); a0.w = fmaf(xv.w, c0, a0.w);
        a1.x = fmaf(xv.x, c1, a1.x); a1.y = fmaf(xv.y, c1, a1.y);
        a1.z = fmaf(xv.z, c1, a1.z); a1.w = fmaf(xv.w, c1, a1.w);
        a2.x = fmaf(xv.x, c2, a2.x); a2.y = fmaf(xv.y, c2, a2.y);
        a2.z = fmaf(xv.z, c2, a2.z); a2.w = fmaf(xv.w, c2, a2.w);
    }

    const float bv0 = bias[0];
    const float bv1 = bias[1];
    const float bv2 = bias[2];

#define CLAMP1(v) fminf(fmaxf((v), -CONV_CLAMP), CONV_CLAMP)
    float4 o0 = make_float4(CLAMP1(a0.x + bv0), CLAMP1(a0.y + bv0),
                            CLAMP1(a0.z + bv0), CLAMP1(a0.w + bv0));
    float4 o1 = make_float4(CLAMP1(a1.x + bv1), CLAMP1(a1.y + bv1),
                            CLAMP1(a1.z + bv1), CLAMP1(a1.w + bv1));
    float4 o2 = make_float4(CLAMP1(a2.x + bv2), CLAMP1(a2.y + bv2),
                            CLAMP1(a2.z + bv2), CLAMP1(a2.w + bv2));
#undef CLAMP1

    float4* __restrict__ out4 = (float4*)out;
    const size_t obase = (size_t)b * COUT * (HW / 4);
    __stcs(&out4[obase + 0 * (HW / 4) + hw4], o0);
    __stcs(&out4[obase + 1 * (HW / 4) + hw4], o1);
    __stcs(&out4[obase + 2 * (HW / 4) + hw4], o2);
}

// ---------------------------------------------------------------------------
// Launch
//   d_in[0] = x        [B, CIN, H, W]  f32
//   d_in[1] = w        [B, WDIM]       f32
//   d_in[2] = weight   [COUT, CIN,1,1] f32
//   d_in[3] = bias     [COUT]          f32
//   d_in[4] = affine_w [CIN, WDIM]     f32
//   d_in[5] = affine_b [CIN]           f32
// ---------------------------------------------------------------------------
extern "C" void kernel_launch(void* const* d_in, const int* in_sizes, int n_in,
                              void* d_out, int out_size)
{
    const float* x        = (const float*)d_in[0];
    const float* w        = (const float*)d_in[1];
    const float* weight   = (const float*)d_in[2];
    const float* bias     = (const float*)d_in[3];
    const float* affine_w = (const float*)d_in[4];
    const float* affine_b = (const float*)d_in[5];
    float* out = (float*)d_out;

    dim3 cgrid(HW / 4 / 256, B_DIM);
    torgb_fused_kernel<<<cgrid, 256>>>(x, w, weight, bias,
                                       affine_w, affine_b, out);
}